// round 3
// baseline (speedup 1.0000x reference)
#include <cuda_runtime.h>
#include <cuda_bf16.h>

// Problem constants (from reference)
#define V_SZ     32000
#define D_SZ     5120
#define T_SZ     32
#define B_SZ     4
#define S_SZ     2048
#define VIS_DIM  768
#define N_SHARED (V_SZ + 2)            // 32002
#define NTOK     (B_SZ * S_SZ)         // 8192
#define NROWS    (B_SZ * T_SZ)         // 128 vision rows

#define THREADS  256
#define VCHUNK   512                   // floats per vision chunk block
#define NVCHUNK  (D_SZ / VCHUNK)       // 10

// Scratch: projected vision rows + usage flags (device globals — no allocation)
__device__ float g_vx[(size_t)NROWS * D_SZ];   // [B*T, D] = 2.6 MB
__device__ int   g_used[NROWS];

// ---------------------------------------------------------------------------
// K0: mark which (b, t) vision rows are referenced. Single block so we can
// zero + fill with __syncthreads (fresh state on every graph replay).
// ---------------------------------------------------------------------------
__global__ __launch_bounds__(1024)
void mark_kernel(const int* __restrict__ text)
{
    __shared__ int s_used[NROWS];
    const int tid = threadIdx.x;
    if (tid < NROWS) s_used[tid] = 0;
    __syncthreads();

    for (int i = tid; i < NTOK; i += 1024) {
        int id = text[i];
        if (id >= N_SHARED) {
            int tv = id - N_SHARED;
            if (tv > T_SZ - 1) tv = T_SZ - 1;
            int b = i / S_SZ;
            s_used[b * T_SZ + tv] = 1;     // benign race
        }
    }
    __syncthreads();
    if (tid < NROWS) g_used[tid] = s_used[tid];
}

// ---------------------------------------------------------------------------
// K1: vx[row] = vis[row] @ fc_w + fc_b, only for marked rows.
// grid (128 rows, 10 chunks) x 256 threads; each thread -> 2 output cols.
// ---------------------------------------------------------------------------
__global__ __launch_bounds__(THREADS)
void vx_kernel(const float* __restrict__ vis,     // [B*T, VIS_DIM]
               const float* __restrict__ fc_w,    // [VIS_DIM, D]
               const float* __restrict__ fc_b)    // [D]
{
    const int row = blockIdx.x;
    if (!g_used[row]) return;

    __shared__ float s_vis[VIS_DIM];
    const int tid = threadIdx.x;

    const float* vrow = vis + (size_t)row * VIS_DIM;
    for (int i = tid; i < VIS_DIM; i += THREADS) s_vis[i] = vrow[i];
    __syncthreads();

    const int col = blockIdx.y * VCHUNK + tid * 2;
    float2 acc = *(const float2*)(fc_b + col);
    const float2* w2 = (const float2*)(fc_w + col);    // row stride D/2 float2

    #pragma unroll 8
    for (int k = 0; k < VIS_DIM; k++) {
        float  a = s_vis[k];
        float2 w = __ldg(&w2[(size_t)k * (D_SZ / 2)]);
        acc.x = fmaf(a, w.x, acc.x);
        acc.y = fmaf(a, w.y, acc.y);
    }
    *(float2*)(g_vx + (size_t)row * D_SZ + col) = acc;
}

// ---------------------------------------------------------------------------
// K2: branch-uniform row gather. One block per token, 256 threads,
// 5 batched LDG.128 -> 5 STG.128, streaming cache hints.
// ---------------------------------------------------------------------------
__global__ __launch_bounds__(THREADS)
void gather_kernel(const int*   __restrict__ text,
                   const float* __restrict__ weight,
                   const float* __restrict__ fig,
                   float*       __restrict__ out)
{
    const int tok = blockIdx.x;
    const int tid = threadIdx.x;

    const int id = __ldg(&text[tok]);

    const float* src;
    if (id < V_SZ) {
        src = weight + (size_t)id * D_SZ;
    } else if (id < N_SHARED) {
        src = fig + (size_t)(id - V_SZ) * D_SZ;
    } else {
        int tv = id - N_SHARED;
        if (tv > T_SZ - 1) tv = T_SZ - 1;
        int b = tok / S_SZ;
        src = g_vx + ((size_t)(b * T_SZ + tv)) * D_SZ;
    }

    const float4* s4 = (const float4*)src;
    float4*       d4 = (float4*)(out + (size_t)tok * D_SZ);

    float4 r0 = __ldcs(s4 + tid);
    float4 r1 = __ldcs(s4 + tid + 1 * THREADS);
    float4 r2 = __ldcs(s4 + tid + 2 * THREADS);
    float4 r3 = __ldcs(s4 + tid + 3 * THREADS);
    float4 r4 = __ldcs(s4 + tid + 4 * THREADS);
    __stcs(d4 + tid,               r0);
    __stcs(d4 + tid + 1 * THREADS, r1);
    __stcs(d4 + tid + 2 * THREADS, r2);
    __stcs(d4 + tid + 3 * THREADS, r3);
    __stcs(d4 + tid + 4 * THREADS, r4);
}

extern "C" void kernel_launch(void* const* d_in, const int* in_sizes, int n_in,
                              void* d_out, int out_size)
{
    const int*   text   = (const int*)  d_in[0];  // [B,S] int32
    const float* vis    = (const float*)d_in[1];  // [B,T,VIS_DIM]
    const float* weight = (const float*)d_in[2];  // [V,D]
    const float* fig    = (const float*)d_in[3];  // [2,D]
    const float* fc_w   = (const float*)d_in[4];  // [VIS_DIM,D]
    const float* fc_b   = (const float*)d_in[5];  // [D]
    float*       out    = (float*)d_out;

    mark_kernel<<<1, 1024>>>(text);
    vx_kernel<<<dim3(NROWS, NVCHUNK), THREADS>>>(vis, fc_w, fc_b);
    gather_kernel<<<NTOK, THREADS>>>(text, weight, fig, out);
}